// round 1
// baseline (speedup 1.0000x reference)
#include <cuda_runtime.h>
#include <cuda_bf16.h>
#include <math.h>

#define B_      16
#define L_      1024
#define DM      512
#define DI      1024
#define DSTATE  128
#define NH      16
#define HD      64
#define CONVD   1280
#define DPROJ   2320
#define NL      6
#define ROWS    (B_*L_)   // 16384

// ---------------- scratch (static device allocations) ----------------
__device__ float g_x  [(size_t)ROWS*DM];
__device__ float g_xln[(size_t)ROWS*DM];
__device__ float g_zx [(size_t)ROWS*DPROJ];
__device__ float g_xbc[(size_t)ROWS*CONVD];
__device__ float g_y  [(size_t)ROWS*DI];
__device__ float g_cos[(size_t)L_*256];
__device__ float g_sin[(size_t)L_*256];

// ---------------- rope table (double-precision trig, per launch) ------
__global__ void k_rope_tab() {
    int i = blockIdx.x * 256 + threadIdx.x;   // i = l*256 + j
    int l = i >> 8, j = i & 255;
    float invf = (float)pow(10000.0, -(double)j / 256.0);
    float f = (float)l * invf;                // fp32 mult, matches jax rounding
    g_cos[i] = (float)cos((double)f);
    g_sin[i] = (float)sin((double)f);
}

// ---------------- input projection (K=17) + rope ----------------------
__global__ void k_inproj_rope(const float* __restrict__ st,
                              const float* __restrict__ W,
                              const float* __restrict__ bias,
                              float* __restrict__ xout) {
    int row = blockIdx.x;            // b*L + l
    int l   = row & (L_ - 1);
    int j   = threadIdx.x;           // pair index 0..255
    __shared__ float s[17];
    if (j < 17) s[j] = st[row * 17 + j];
    __syncthreads();
    int c0 = j << 1;
    float2 bv = ((const float2*)bias)[j];
    float a0 = bv.x, a1 = bv.y;
#pragma unroll
    for (int i = 0; i < 17; i++) {
        float2 wv = ((const float2*)(W + i * DM))[j];
        a0 = fmaf(s[i], wv.x, a0);
        a1 = fmaf(s[i], wv.y, a1);
    }
    float cs = g_cos[l * 256 + j];
    float sn = g_sin[l * 256 + j];
    xout[(size_t)row * DM + c0]     = a0 * cs - a1 * sn;
    xout[(size_t)row * DM + c0 + 1] = a0 * sn + a1 * cs;
}

// ---------------- layernorm over 512 ---------------------------------
__global__ void __launch_bounds__(128) k_layernorm(
        const float* __restrict__ x, float* __restrict__ out,
        const float* __restrict__ g, const float* __restrict__ b) {
    int row = blockIdx.x;
    int tid = threadIdx.x;           // 128 threads, 4 floats each
    float4 v = ((const float4*)(x + (size_t)row * DM))[tid];
    float s  = v.x + v.y + v.z + v.w;
    float ss = v.x * v.x + v.y * v.y + v.z * v.z + v.w * v.w;
#pragma unroll
    for (int o = 16; o; o >>= 1) {
        s  += __shfl_xor_sync(0xFFFFFFFFu, s, o);
        ss += __shfl_xor_sync(0xFFFFFFFFu, ss, o);
    }
    __shared__ float sw[4], ssw[4];
    if ((tid & 31) == 0) { sw[tid >> 5] = s; ssw[tid >> 5] = ss; }
    __syncthreads();
    s  = sw[0] + sw[1] + sw[2] + sw[3];
    ss = ssw[0] + ssw[1] + ssw[2] + ssw[3];
    float mu  = s * (1.0f / DM);
    float var = ss * (1.0f / DM) - mu * mu;
    float r   = rsqrtf(var + 1e-5f);
    float4 gv = ((const float4*)g)[tid];
    float4 bv = ((const float4*)b)[tid];
    float4 o;
    o.x = (v.x - mu) * r * gv.x + bv.x;
    o.y = (v.y - mu) * r * gv.y + bv.y;
    o.z = (v.z - mu) * r * gv.z + bv.z;
    o.w = (v.w - mu) * r * gv.w + bv.w;
    ((float4*)(out + (size_t)row * DM))[tid] = o;
}

// ---------------- SGEMM 128x128x8, 256 threads, 8x8 microtile ---------
// EPI: 0 = plain, 1 = += residual E[row*N+col], 2 = += bias E[col]
template<int EPI>
__global__ void __launch_bounds__(256) k_sgemm(
        const float* __restrict__ A, const float* __restrict__ B,
        float* __restrict__ C, const float* __restrict__ E,
        int M, int N, int K) {
    __shared__ __align__(16) float As[2][8][128];
    __shared__ __align__(16) float Bs[2][8][128];
    int tid = threadIdx.x;
    int m0 = blockIdx.y << 7, n0 = blockIdx.x << 7;
    int arow = tid >> 1,  aseg = (tid & 1) << 2;
    int brow = tid >> 5,  bcol = (tid & 31) << 2;
    const float* Ap = A + (size_t)(m0 + arow) * K + aseg;
    const float* Bp = B + (size_t)brow * N + n0 + bcol;
    bool bfull = (n0 + bcol + 3) < N;
    int KT = K >> 3;
    float4 ra, rb;

#define LDB_GUARDED(dst, koff) do {                                   \
        const float* _bp = Bp + (size_t)(koff) * N;                   \
        if (bfull) dst = *(const float4*)_bp;                          \
        else {                                                        \
            dst.x = (n0 + bcol + 0 < N) ? _bp[0] : 0.0f;              \
            dst.y = (n0 + bcol + 1 < N) ? _bp[1] : 0.0f;              \
            dst.z = (n0 + bcol + 2 < N) ? _bp[2] : 0.0f;              \
            dst.w = (n0 + bcol + 3 < N) ? _bp[3] : 0.0f;              \
        }                                                             \
    } while (0)

    ra = *(const float4*)Ap;
    LDB_GUARDED(rb, 0);
    As[0][aseg + 0][arow] = ra.x;
    As[0][aseg + 1][arow] = ra.y;
    As[0][aseg + 2][arow] = ra.z;
    As[0][aseg + 3][arow] = ra.w;
    *(float4*)&Bs[0][brow][bcol] = rb;
    __syncthreads();

    int tx = tid & 15, ty = tid >> 4;
    float acc[8][8];
#pragma unroll
    for (int i = 0; i < 8; i++)
#pragma unroll
        for (int j = 0; j < 8; j++) acc[i][j] = 0.0f;

    for (int kt = 0; kt < KT; kt++) {
        int cur = kt & 1;
        if (kt + 1 < KT) {
            ra = *(const float4*)(Ap + ((kt + 1) << 3));
            LDB_GUARDED(rb, (kt + 1) << 3);
        }
#pragma unroll
        for (int k = 0; k < 8; k++) {
            float4 a0 = *(const float4*)&As[cur][k][ty << 3];
            float4 a1 = *(const float4*)&As[cur][k][(ty << 3) + 4];
            float4 b0 = *(const float4*)&Bs[cur][k][tx << 3];
            float4 b1 = *(const float4*)&Bs[cur][k][(tx << 3) + 4];
            float av[8] = {a0.x, a0.y, a0.z, a0.w, a1.x, a1.y, a1.z, a1.w};
            float bv[8] = {b0.x, b0.y, b0.z, b0.w, b1.x, b1.y, b1.z, b1.w};
#pragma unroll
            for (int i = 0; i < 8; i++)
#pragma unroll
                for (int j = 0; j < 8; j++)
                    acc[i][j] = fmaf(av[i], bv[j], acc[i][j]);
        }
        if (kt + 1 < KT) {
            int nb = (kt + 1) & 1;
            As[nb][aseg + 0][arow] = ra.x;
            As[nb][aseg + 1][arow] = ra.y;
            As[nb][aseg + 2][arow] = ra.z;
            As[nb][aseg + 3][arow] = ra.w;
            *(float4*)&Bs[nb][brow][bcol] = rb;
            __syncthreads();
        }
    }
#undef LDB_GUARDED

#pragma unroll
    for (int i = 0; i < 8; i++) {
        int row = m0 + (ty << 3) + i;
        size_t base = (size_t)row * N;
#pragma unroll
        for (int j = 0; j < 8; j++) {
            int col = n0 + (tx << 3) + j;
            if (col < N) {
                float v = acc[i][j];
                if (EPI == 1) v += E[base + col];
                else if (EPI == 2) v += E[col];
                C[base + col] = v;
            }
        }
    }
}

// ---------------- depthwise causal conv (K=4) + silu ------------------
__global__ void k_conv(const float* __restrict__ zx, float* __restrict__ xbc,
                       const float* __restrict__ w, const float* __restrict__ cb) {
    int c  = blockIdx.x * 128 + threadIdx.x;   // 0..1279
    int b  = blockIdx.z;
    int l0 = blockIdx.y * 32;
    float w0 = w[c * 4 + 0], w1 = w[c * 4 + 1];
    float w2 = w[c * 4 + 2], w3 = w[c * 4 + 3];
    float bias = cb[c];
    const float* xin = zx + ((size_t)b * L_) * DPROJ + 1024 + c;
    float* xo = xbc + ((size_t)b * L_) * CONVD + c;
    float x0 = (l0 >= 3) ? xin[(size_t)(l0 - 3) * DPROJ] : 0.0f;
    float x1 = (l0 >= 2) ? xin[(size_t)(l0 - 2) * DPROJ] : 0.0f;
    float x2 = (l0 >= 1) ? xin[(size_t)(l0 - 1) * DPROJ] : 0.0f;
    for (int i = 0; i < 32; i++) {
        int l = l0 + i;
        float x3 = xin[(size_t)l * DPROJ];
        float v = bias + w0 * x0 + w1 * x1 + w2 * x2 + w3 * x3;
        v = v / (1.0f + expf(-v));             // silu
        xo[(size_t)l * CONVD] = v;
        x0 = x1; x1 = x2; x2 = x3;
    }
}

// ---------------- sequential selective scan ---------------------------
// block = (h, b); 256 threads = 64 p  x 4 n-groups (32 n each, in regs)
__global__ void __launch_bounds__(256) k_scan(
        const float* __restrict__ zx, const float* __restrict__ xbc,
        const float* __restrict__ dt_bias, const float* __restrict__ A_log,
        float* __restrict__ y) {
    int h = blockIdx.x, b = blockIdx.y;
    int tid = threadIdx.x;
    __shared__ float dt_s[L_];
    __shared__ float dec_s[L_];
    __shared__ __align__(16) float stage[2][320];   // [B(128) C(128) x(64)]

    float Ah  = -expf(A_log[h]);
    float dtb = dt_bias[h];
    const float* zrow = zx + ((size_t)b * L_) * DPROJ + 2304 + h;
    for (int l = tid; l < L_; l += 256) {
        float u  = zrow[(size_t)l * DPROJ] + dtb;
        float sp = (u > 20.0f) ? u : log1pf(expf(u));
        dt_s[l]  = sp;
        dec_s[l] = expf(sp * Ah);
    }
    const float* xrow = xbc + ((size_t)b * L_) * CONVD;
    stage[0][tid] = xrow[1024 + tid];
    if (tid < 64) stage[0][256 + tid] = xrow[h * HD + tid];
    __syncthreads();

    int p = tid >> 2, ng = tid & 3;
    float s[32];
#pragma unroll
    for (int i = 0; i < 32; i++) s[i] = 0.0f;
    float* yout = y + ((size_t)b * L_) * DI + h * HD + p;

    for (int l = 0; l < L_; l++) {
        int cur = l & 1, nxt = cur ^ 1;
        float pA = 0.0f, pX = 0.0f;
        if (l + 1 < L_) {
            const float* nrow = xrow + (size_t)(l + 1) * CONVD;
            pA = nrow[1024 + tid];
            if (tid < 64) pX = nrow[h * HD + tid];
        }
        float dec = dec_s[l];
        float dtx = dt_s[l] * stage[cur][256 + p];
        const float4* B4 = (const float4*)&stage[cur][ng * 32];
        const float4* C4 = (const float4*)&stage[cur][128 + ng * 32];
        float yp = 0.0f;
#pragma unroll
        for (int i = 0; i < 8; i++) {
            float4 bv = B4[i], cv = C4[i];
            s[4*i+0] = fmaf(s[4*i+0], dec, dtx * bv.x); yp = fmaf(s[4*i+0], cv.x, yp);
            s[4*i+1] = fmaf(s[4*i+1], dec, dtx * bv.y); yp = fmaf(s[4*i+1], cv.y, yp);
            s[4*i+2] = fmaf(s[4*i+2], dec, dtx * bv.z); yp = fmaf(s[4*i+2], cv.z, yp);
            s[4*i+3] = fmaf(s[4*i+3], dec, dtx * bv.w); yp = fmaf(s[4*i+3], cv.w, yp);
        }
        yp += __shfl_xor_sync(0xFFFFFFFFu, yp, 1);
        yp += __shfl_xor_sync(0xFFFFFFFFu, yp, 2);
        if (ng == 0) yout[(size_t)l * DI] = yp;
        if (l + 1 < L_) {
            stage[nxt][tid] = pA;
            if (tid < 64) stage[nxt][256 + tid] = pX;
        }
        __syncthreads();
    }
}

// ---------------- y = (y + D*xs)*silu(z), RMS-norm, *rms_w ------------
__global__ void __launch_bounds__(256) k_postscan(
        float* __restrict__ y, const float* __restrict__ xbc,
        const float* __restrict__ zx, const float* __restrict__ Dp,
        const float* __restrict__ rmsw) {
    int row = blockIdx.x, tid = threadIdx.x;   // 256 threads, 4 floats each
    float4 yv = ((const float4*)(y   + (size_t)row * DI))[tid];
    float4 xv = ((const float4*)(xbc + (size_t)row * CONVD))[tid];
    float4 zv = ((const float4*)(zx  + (size_t)row * DPROJ))[tid];
    float D = Dp[tid >> 4];
    float4 v;
    v.x = (yv.x + D * xv.x) * (zv.x / (1.0f + expf(-zv.x)));
    v.y = (yv.y + D * xv.y) * (zv.y / (1.0f + expf(-zv.y)));
    v.z = (yv.z + D * xv.z) * (zv.z / (1.0f + expf(-zv.z)));
    v.w = (yv.w + D * xv.w) * (zv.w / (1.0f + expf(-zv.w)));
    float ss = v.x * v.x + v.y * v.y + v.z * v.z + v.w * v.w;
#pragma unroll
    for (int o = 16; o; o >>= 1) ss += __shfl_xor_sync(0xFFFFFFFFu, ss, o);
    __shared__ float sm[8];
    if ((tid & 31) == 0) sm[tid >> 5] = ss;
    __syncthreads();
    float tot = sm[0] + sm[1] + sm[2] + sm[3] + sm[4] + sm[5] + sm[6] + sm[7];
    float sc = rsqrtf(tot * (1.0f / DI) + 1e-5f);
    float4 gw = ((const float4*)rmsw)[tid];
    v.x *= sc * gw.x; v.y *= sc * gw.y; v.z *= sc * gw.z; v.w *= sc * gw.w;
    ((float4*)(y + (size_t)row * DI))[tid] = v;
}

// ---------------- launch ----------------------------------------------
extern "C" void kernel_launch(void* const* d_in, const int* in_sizes, int n_in,
                              void* d_out, int out_size) {
    const float* states  = (const float*)d_in[0];
    const float* ipw     = (const float*)d_in[1];
    const float* ipb     = (const float*)d_in[2];
    const float* ln_g    = (const float*)d_in[3];
    const float* ln_b    = (const float*)d_in[4];
    const float* in_w    = (const float*)d_in[5];
    const float* conv_w  = (const float*)d_in[6];
    const float* conv_b  = (const float*)d_in[7];
    const float* dt_bias = (const float*)d_in[8];
    const float* A_log   = (const float*)d_in[9];
    const float* D_par   = (const float*)d_in[10];
    const float* rms_w   = (const float*)d_in[11];
    const float* out_w   = (const float*)d_in[12];
    const float* pg      = (const float*)d_in[13];
    const float* pb      = (const float*)d_in[14];
    const float* opw     = (const float*)d_in[15];
    const float* opb     = (const float*)d_in[16];

    float *x, *xln, *zx, *xbc, *y;
    cudaGetSymbolAddress((void**)&x,   g_x);
    cudaGetSymbolAddress((void**)&xln, g_xln);
    cudaGetSymbolAddress((void**)&zx,  g_zx);
    cudaGetSymbolAddress((void**)&xbc, g_xbc);
    cudaGetSymbolAddress((void**)&y,   g_y);

    k_rope_tab<<<L_, 256>>>();
    k_inproj_rope<<<ROWS, 256>>>(states, ipw, ipb, x);

    for (int l = 0; l < NL; l++) {
        k_layernorm<<<ROWS, 128>>>(x, xln, ln_g + l * DM, ln_b + l * DM);
        k_sgemm<0><<<dim3(19, 128), 256>>>(xln, in_w + (size_t)l * DM * DPROJ,
                                           zx, nullptr, ROWS, DPROJ, DM);
        k_conv<<<dim3(10, 32, 16), 128>>>(zx, xbc, conv_w + l * CONVD * 4,
                                          conv_b + l * CONVD);
        k_scan<<<dim3(16, 16), 256>>>(zx, xbc, dt_bias + l * NH,
                                      A_log + l * NH, y);
        k_postscan<<<ROWS, 256>>>(y, xbc, zx, D_par + l * NH, rms_w + l * DI);
        k_sgemm<1><<<dim3(4, 128), 256>>>(y, out_w + (size_t)l * DI * DM,
                                          x, x, ROWS, DM, DI);
    }
    k_layernorm<<<ROWS, 128>>>(x, xln, pg, pb);
    k_sgemm<2><<<dim3(4, 128), 256>>>(xln, opw, (float*)d_out, opb,
                                      ROWS, DM, DM);
}

// round 2
// speedup vs baseline: 1.0170x; 1.0170x over previous
#include <cuda_runtime.h>
#include <cuda_bf16.h>
#include <math.h>
#include <stdint.h>

#define B_      16
#define L_      1024
#define DM      512
#define DI      1024
#define DSTATE  128
#define NH      16
#define HD      64
#define CONVD   1280
#define DPROJ   2320
#define NL      6
#define ROWS    (B_*L_)   // 16384

// ---------------- scratch (static device allocations) ----------------
__device__ float g_x  [(size_t)ROWS*DM];
__device__ float g_xln[(size_t)ROWS*DM];
__device__ float g_zx [(size_t)ROWS*DPROJ];
__device__ float g_xbc[(size_t)ROWS*CONVD];
__device__ float g_y  [(size_t)ROWS*DI];
__device__ float g_cos[(size_t)L_*256];
__device__ float g_sin[(size_t)L_*256];

// ---------------- rope table (double-precision trig, per launch) ------
__global__ void k_rope_tab() {
    int i = blockIdx.x * 256 + threadIdx.x;   // i = l*256 + j
    int l = i >> 8, j = i & 255;
    float invf = (float)pow(10000.0, -(double)j / 256.0);
    float f = (float)l * invf;                // fp32 mult, matches jax rounding
    g_cos[i] = (float)cos((double)f);
    g_sin[i] = (float)sin((double)f);
}

// ---------------- input projection (K=17) + rope ----------------------
__global__ void k_inproj_rope(const float* __restrict__ st,
                              const float* __restrict__ W,
                              const float* __restrict__ bias,
                              float* __restrict__ xout) {
    int row = blockIdx.x;            // b*L + l
    int l   = row & (L_ - 1);
    int j   = threadIdx.x;           // pair index 0..255
    __shared__ float s[17];
    if (j < 17) s[j] = st[row * 17 + j];
    __syncthreads();
    int c0 = j << 1;
    float2 bv = ((const float2*)bias)[j];
    float a0 = bv.x, a1 = bv.y;
#pragma unroll
    for (int i = 0; i < 17; i++) {
        float2 wv = ((const float2*)(W + i * DM))[j];
        a0 = fmaf(s[i], wv.x, a0);
        a1 = fmaf(s[i], wv.y, a1);
    }
    float cs = g_cos[l * 256 + j];
    float sn = g_sin[l * 256 + j];
    xout[(size_t)row * DM + c0]     = a0 * cs - a1 * sn;
    xout[(size_t)row * DM + c0 + 1] = a0 * sn + a1 * cs;
}

// ---------------- layernorm over 512 ---------------------------------
__global__ void __launch_bounds__(128) k_layernorm(
        const float* __restrict__ x, float* __restrict__ out,
        const float* __restrict__ g, const float* __restrict__ b) {
    int row = blockIdx.x;
    int tid = threadIdx.x;           // 128 threads, 4 floats each
    float4 v = ((const float4*)(x + (size_t)row * DM))[tid];
    float s  = v.x + v.y + v.z + v.w;
    float ss = v.x * v.x + v.y * v.y + v.z * v.z + v.w * v.w;
#pragma unroll
    for (int o = 16; o; o >>= 1) {
        s  += __shfl_xor_sync(0xFFFFFFFFu, s, o);
        ss += __shfl_xor_sync(0xFFFFFFFFu, ss, o);
    }
    __shared__ float sw[4], ssw[4];
    if ((tid & 31) == 0) { sw[tid >> 5] = s; ssw[tid >> 5] = ss; }
    __syncthreads();
    s  = sw[0] + sw[1] + sw[2] + sw[3];
    ss = ssw[0] + ssw[1] + ssw[2] + ssw[3];
    float mu  = s * (1.0f / DM);
    float var = ss * (1.0f / DM) - mu * mu;
    float r   = rsqrtf(var + 1e-5f);
    float4 gv = ((const float4*)g)[tid];
    float4 bv = ((const float4*)b)[tid];
    float4 o;
    o.x = (v.x - mu) * r * gv.x + bv.x;
    o.y = (v.y - mu) * r * gv.y + bv.y;
    o.z = (v.z - mu) * r * gv.z + bv.z;
    o.w = (v.w - mu) * r * gv.w + bv.w;
    ((float4*)(out + (size_t)row * DM))[tid] = o;
}

// ---------------- tensor-core GEMM helpers ----------------------------
__device__ __forceinline__ unsigned smem_u32(const void* p) {
    return (unsigned)__cvta_generic_to_shared(p);
}
__device__ __forceinline__ void ldsm_x4(unsigned addr, unsigned &r0, unsigned &r1,
                                        unsigned &r2, unsigned &r3) {
    asm volatile("ldmatrix.sync.aligned.m8n8.x4.shared.b16 {%0,%1,%2,%3}, [%4];"
        : "=r"(r0), "=r"(r1), "=r"(r2), "=r"(r3) : "r"(addr));
}
__device__ __forceinline__ void ldsm_x2(unsigned addr, unsigned &r0, unsigned &r1) {
    asm volatile("ldmatrix.sync.aligned.m8n8.x2.shared.b16 {%0,%1}, [%2];"
        : "=r"(r0), "=r"(r1) : "r"(addr));
}
__device__ __forceinline__ void mma_bf16(float* c, unsigned a0, unsigned a1,
                                         unsigned a2, unsigned a3,
                                         unsigned b0, unsigned b1) {
    asm volatile(
        "mma.sync.aligned.m16n8k16.row.col.f32.bf16.bf16.f32 "
        "{%0,%1,%2,%3}, {%4,%5,%6,%7}, {%8,%9}, {%0,%1,%2,%3};"
        : "+f"(c[0]), "+f"(c[1]), "+f"(c[2]), "+f"(c[3])
        : "r"(a0), "r"(a1), "r"(a2), "r"(a3), "r"(b0), "r"(b1));
}
__device__ __forceinline__ void split_pack(float a, float b,
                                           uint32_t &h, uint32_t &l) {
    __nv_bfloat16 ha = __float2bfloat16(a);
    __nv_bfloat16 hb = __float2bfloat16(b);
    float la = a - __bfloat162float(ha);
    float lb = b - __bfloat162float(hb);
    __nv_bfloat162 hp; hp.x = ha; hp.y = hb;
    __nv_bfloat162 lp; lp.x = __float2bfloat16(la); lp.y = __float2bfloat16(lb);
    h = *reinterpret_cast<uint32_t*>(&hp);
    l = *reinterpret_cast<uint32_t*>(&lp);
}

// ---------------- GEMM 128x128 tile, bf16-split 3-pass MMA ------------
// EPI: 0 = plain, 1 = += residual E[row*N+col], 2 = += bias E[col]
// Requires K % 16 == 0, M % 128 == 0, N % 4 == 0.
template<int EPI>
__global__ void __launch_bounds__(256) k_gemm_tc(
        const float* __restrict__ A, const float* __restrict__ B,
        float* __restrict__ C, const float* __restrict__ E,
        int M, int N, int K) {
    // pitch 12 words (48B) per 16-bf16 row: ldmatrix rows hit disjoint bank groups
    __shared__ uint32_t As_h[2][128][12];
    __shared__ uint32_t As_l[2][128][12];
    __shared__ uint32_t Bs_h[2][128][12];
    __shared__ uint32_t Bs_l[2][128][12];

    int tid  = threadIdx.x;
    int lane = tid & 31, wid = tid >> 5;
    int wm = wid >> 2, wn = wid & 3;              // warp grid 2 (M) x 4 (N)
    int m0 = blockIdx.y << 7, n0 = blockIdx.x << 7;

    // global loaders: A 128x16 (fp32), B 16x128 (fp32) per k-chunk
    int arow = tid >> 1, aseg = (tid & 1) << 3;   // two float4 at k = aseg, aseg+4
    int brow = tid >> 4, bcol = (tid & 15) << 3;  // two float4 at n = bcol, bcol+4
    const float* Ap = A + (size_t)(m0 + arow) * K + aseg;
    const float* Bp = B + (size_t)brow * N + n0 + bcol;
    bool bok0 = (n0 + bcol     + 3) < N;
    bool bok1 = (n0 + bcol + 4 + 3) < N;

    float4 ra0, ra1, rb0, rb1;
#define LOADG(k0) do {                                                   \
        ra0 = *(const float4*)(Ap + (k0));                               \
        ra1 = *(const float4*)(Ap + (k0) + 4);                           \
        const float* _bp = Bp + (size_t)(k0) * N;                        \
        rb0 = bok0 ? *(const float4*)_bp       : make_float4(0,0,0,0);   \
        rb1 = bok1 ? *(const float4*)(_bp + 4) : make_float4(0,0,0,0);   \
    } while (0)

#define STORE_SMEM(buf) do {                                             \
        int _aw = aseg >> 1;                                             \
        float _fa[8] = {ra0.x, ra0.y, ra0.z, ra0.w,                      \
                        ra1.x, ra1.y, ra1.z, ra1.w};                     \
        _Pragma("unroll")                                                \
        for (int _i = 0; _i < 4; _i++) {                                 \
            uint32_t _h, _l;                                             \
            split_pack(_fa[2*_i], _fa[2*_i+1], _h, _l);                  \
            As_h[buf][arow][_aw + _i] = _h;                              \
            As_l[buf][arow][_aw + _i] = _l;                              \
        }                                                                \
        __nv_bfloat16* _bh = (__nv_bfloat16*)&Bs_h[buf][0][0];           \
        __nv_bfloat16* _bl = (__nv_bfloat16*)&Bs_l[buf][0][0];           \
        float _fb[8] = {rb0.x, rb0.y, rb0.z, rb0.w,                      \
                        rb1.x, rb1.y, rb1.z, rb1.w};                     \
        _Pragma("unroll")                                                \
        for (int _j = 0; _j < 8; _j++) {                                 \
            int _n = bcol + _j;                                          \
            float _v = _fb[_j];                                          \
            __nv_bfloat16 _vh = __float2bfloat16(_v);                    \
            float _vl = _v - __bfloat162float(_vh);                      \
            _bh[_n * 24 + brow] = _vh;                                   \
            _bl[_n * 24 + brow] = __float2bfloat16(_vl);                 \
        }                                                                \
    } while (0)

    LOADG(0);
    STORE_SMEM(0);
    __syncthreads();

    float acc[4][4][4];
#pragma unroll
    for (int i = 0; i < 4; i++)
#pragma unroll
        for (int j = 0; j < 4; j++)
#pragma unroll
            for (int k = 0; k < 4; k++) acc[i][j][k] = 0.0f;

    // per-thread ldmatrix offsets (bytes), row pitch 48B
    unsigned offA = (unsigned)((wm * 64 + (lane & 15)) * 48 + ((lane >> 4) & 1) * 16);
    unsigned offB = (unsigned)((wn * 32 + (lane & 7))  * 48 + ((lane >> 3) & 1) * 16);
    unsigned baseAh = smem_u32(&As_h[0][0][0]) + offA;
    unsigned baseAl = smem_u32(&As_l[0][0][0]) + offA;
    unsigned baseBh = smem_u32(&Bs_h[0][0][0]) + offB;
    unsigned baseBl = smem_u32(&Bs_l[0][0][0]) + offB;

    int KT = K >> 4;
    for (int kt = 0; kt < KT; kt++) {
        unsigned cb = (kt & 1) ? 6144u : 0u;
        if (kt + 1 < KT) LOADG((kt + 1) << 4);

        unsigned bh[4][2], bl[4][2];
#pragma unroll
        for (int nt = 0; nt < 4; nt++) {
            ldsm_x2(baseBh + cb + nt * 384, bh[nt][0], bh[nt][1]);
            ldsm_x2(baseBl + cb + nt * 384, bl[nt][0], bl[nt][1]);
        }
#pragma unroll
        for (int mt = 0; mt < 4; mt++) {
            unsigned ah0, ah1, ah2, ah3, al0, al1, al2, al3;
            ldsm_x4(baseAh + cb + mt * 768, ah0, ah1, ah2, ah3);
            ldsm_x4(baseAl + cb + mt * 768, al0, al1, al2, al3);
#pragma unroll
            for (int nt = 0; nt < 4; nt++) {
                mma_bf16(acc[mt][nt], ah0, ah1, ah2, ah3, bh[nt][0], bh[nt][1]);
                mma_bf16(acc[mt][nt], ah0, ah1, ah2, ah3, bl[nt][0], bl[nt][1]);
                mma_bf16(acc[mt][nt], al0, al1, al2, al3, bh[nt][0], bh[nt][1]);
            }
        }
        if (kt + 1 < KT) {
            STORE_SMEM((kt + 1) & 1);
            __syncthreads();
        }
    }
#undef LOADG
#undef STORE_SMEM

    // epilogue
#pragma unroll
    for (int mt = 0; mt < 4; mt++) {
        int r0 = m0 + wm * 64 + mt * 16 + (lane >> 2);
#pragma unroll
        for (int nt = 0; nt < 4; nt++) {
            int col = n0 + wn * 32 + nt * 8 + ((lane & 3) << 1);
            if (col < N) {
                size_t i0 = (size_t)r0 * N + col;
                size_t i1 = (size_t)(r0 + 8) * N + col;
                float2 v0 = make_float2(acc[mt][nt][0], acc[mt][nt][1]);
                float2 v1 = make_float2(acc[mt][nt][2], acc[mt][nt][3]);
                if (EPI == 1) {
                    v0.x += E[i0]; v0.y += E[i0 + 1];
                    v1.x += E[i1]; v1.y += E[i1 + 1];
                } else if (EPI == 2) {
                    v0.x += E[col]; v0.y += E[col + 1];
                    v1.x += E[col]; v1.y += E[col + 1];
                }
                *(float2*)(C + i0) = v0;
                *(float2*)(C + i1) = v1;
            }
        }
    }
}

// ---------------- depthwise causal conv (K=4) + silu ------------------
__global__ void k_conv(const float* __restrict__ zx, float* __restrict__ xbc,
                       const float* __restrict__ w, const float* __restrict__ cb) {
    int c  = blockIdx.x * 128 + threadIdx.x;   // 0..1279
    int b  = blockIdx.z;
    int l0 = blockIdx.y * 32;
    float w0 = w[c * 4 + 0], w1 = w[c * 4 + 1];
    float w2 = w[c * 4 + 2], w3 = w[c * 4 + 3];
    float bias = cb[c];
    const float* xin = zx + ((size_t)b * L_) * DPROJ + 1024 + c;
    float* xo = xbc + ((size_t)b * L_) * CONVD + c;
    float x0 = (l0 >= 3) ? xin[(size_t)(l0 - 3) * DPROJ] : 0.0f;
    float x1 = (l0 >= 2) ? xin[(size_t)(l0 - 2) * DPROJ] : 0.0f;
    float x2 = (l0 >= 1) ? xin[(size_t)(l0 - 1) * DPROJ] : 0.0f;
    for (int i = 0; i < 32; i++) {
        int l = l0 + i;
        float x3 = xin[(size_t)l * DPROJ];
        float v = bias + w0 * x0 + w1 * x1 + w2 * x2 + w3 * x3;
        v = v / (1.0f + expf(-v));             // silu
        xo[(size_t)l * CONVD] = v;
        x0 = x1; x1 = x2; x2 = x3;
    }
}

// ---------------- sequential selective scan ---------------------------
// block = (h, b); 256 threads = 64 p  x 4 n-groups (32 n each, in regs)
__global__ void __launch_bounds__(256) k_scan(
        const float* __restrict__ zx, const float* __restrict__ xbc,
        const float* __restrict__ dt_bias, const float* __restrict__ A_log,
        float* __restrict__ y) {
    int h = blockIdx.x, b = blockIdx.y;
    int tid = threadIdx.x;
    __shared__ float dt_s[L_];
    __shared__ float dec_s[L_];
    __shared__ __align__(16) float stage[2][320];   // [B(128) C(128) x(64)]

    float Ah  = -expf(A_log[h]);
    float dtb = dt_bias[h];
    const float* zrow = zx + ((size_t)b * L_) * DPROJ + 2304 + h;
    for (int l = tid; l < L_; l += 256) {
        float u  = zrow[(size_t)l * DPROJ] + dtb;
        float sp = (u > 20.0f) ? u : log1pf(expf(u));
        dt_s[l]  = sp;
        dec_s[l] = expf(sp * Ah);
    }
    const float* xrow = xbc + ((size_t)b * L_) * CONVD;
    stage[0][tid] = xrow[1024 + tid];
    if (tid < 64) stage[0][256 + tid] = xrow[h * HD + tid];
    __syncthreads();

    int p = tid >> 2, ng = tid & 3;
    float s[32];
#pragma unroll
    for (int i = 0; i < 32; i++) s[i] = 0.0f;
    float* yout = y + ((size_t)b * L_) * DI + h * HD + p;

    for (int l = 0; l < L_; l++) {
        int cur = l & 1, nxt = cur ^ 1;
        float pA = 0.0f, pX = 0.0f;
        if (l + 1 < L_) {
            const float* nrow = xrow + (size_t)(l + 1) * CONVD;
            pA = nrow[1024 + tid];
            if (tid < 64) pX = nrow[h * HD + tid];
        }
        float dec = dec_s[l];
        float dtx = dt_s[l] * stage[cur][256 + p];
        const float4* B4 = (const float4*)&stage[cur][ng * 32];
        const float4* C4 = (const float4*)&stage[cur][128 + ng * 32];
        float yp = 0.0f;
#pragma unroll
        for (int i = 0; i < 8; i++) {
            float4 bv = B4[i], cv = C4[i];
            s[4*i+0] = fmaf(s[4*i+0], dec, dtx * bv.x); yp = fmaf(s[4*i+0], cv.x, yp);
            s[4*i+1] = fmaf(s[4*i+1], dec, dtx * bv.y); yp = fmaf(s[4*i+1], cv.y, yp);
            s[4*i+2] = fmaf(s[4*i+2], dec, dtx * bv.z); yp = fmaf(s[4*i+2], cv.z, yp);
            s[4*i+3] = fmaf(s[4*i+3], dec, dtx * bv.w); yp = fmaf(s[4*i+3], cv.w, yp);
        }
        yp += __shfl_xor_sync(0xFFFFFFFFu, yp, 1);
        yp += __shfl_xor_sync(0xFFFFFFFFu, yp, 2);
        if (ng == 0) yout[(size_t)l * DI] = yp;
        if (l + 1 < L_) {
            stage[nxt][tid] = pA;
            if (tid < 64) stage[nxt][256 + tid] = pX;
        }
        __syncthreads();
    }
}

// ---------------- y = (y + D*xs)*silu(z), RMS-norm, *rms_w ------------
__global__ void __launch_bounds__(256) k_postscan(
        float* __restrict__ y, const float* __restrict__ xbc,
        const float* __restrict__ zx, const float* __restrict__ Dp,
        const float* __restrict__ rmsw) {
    int row = blockIdx.x, tid = threadIdx.x;   // 256 threads, 4 floats each
    float4 yv = ((const float4*)(y   + (size_t)row * DI))[tid];
    float4 xv = ((const float4*)(xbc + (size_t)row * CONVD))[tid];
    float4 zv = ((const float4*)(zx  + (size_t)row * DPROJ))[tid];
    float D = Dp[tid >> 4];
    float4 v;
    v.x = (yv.x + D * xv.x) * (zv.x / (1.0f + expf(-zv.x)));
    v.y = (yv.y + D * xv.y) * (zv.y / (1.0f + expf(-zv.y)));
    v.z = (yv.z + D * xv.z) * (zv.z / (1.0f + expf(-zv.z)));
    v.w = (yv.w + D * xv.w) * (zv.w / (1.0f + expf(-zv.w)));
    float ss = v.x * v.x + v.y * v.y + v.z * v.z + v.w * v.w;
#pragma unroll
    for (int o = 16; o; o >>= 1) ss += __shfl_xor_sync(0xFFFFFFFFu, ss, o);
    __shared__ float sm[8];
    if ((tid & 31) == 0) sm[tid >> 5] = ss;
    __syncthreads();
    float tot = sm[0] + sm[1] + sm[2] + sm[3] + sm[4] + sm[5] + sm[6] + sm[7];
    float sc = rsqrtf(tot * (1.0f / DI) + 1e-5f);
    float4 gw = ((const float4*)rmsw)[tid];
    v.x *= sc * gw.x; v.y *= sc * gw.y; v.z *= sc * gw.z; v.w *= sc * gw.w;
    ((float4*)(y + (size_t)row * DI))[tid] = v;
}

// ---------------- launch ----------------------------------------------
extern "C" void kernel_launch(void* const* d_in, const int* in_sizes, int n_in,
                              void* d_out, int out_size) {
    const float* states  = (const float*)d_in[0];
    const float* ipw     = (const float*)d_in[1];
    const float* ipb     = (const float*)d_in[2];
    const float* ln_g    = (const float*)d_in[3];
    const float* ln_b    = (const float*)d_in[4];
    const float* in_w    = (const float*)d_in[5];
    const float* conv_w  = (const float*)d_in[6];
    const float* conv_b  = (const float*)d_in[7];
    const float* dt_bias = (const float*)d_in[8];
    const float* A_log   = (const float*)d_in[9];
    const float* D_par   = (const float*)d_in[10];
    const float* rms_w   = (const float*)d_in[11];
    const float* out_w   = (const float*)d_in[12];
    const float* pg      = (const float*)d_in[13];
    const float* pb      = (const float*)d_in[14];
    const float* opw     = (const float*)d_in[15];
    const float* opb     = (const float*)d_in[16];

    float *x, *xln, *zx, *xbc, *y;
    cudaGetSymbolAddress((void**)&x,   g_x);
    cudaGetSymbolAddress((void**)&xln, g_xln);
    cudaGetSymbolAddress((void**)&zx,  g_zx);
    cudaGetSymbolAddress((void**)&xbc, g_xbc);
    cudaGetSymbolAddress((void**)&y,   g_y);

    k_rope_tab<<<L_, 256>>>();
    k_inproj_rope<<<ROWS, 256>>>(states, ipw, ipb, x);

    for (int l = 0; l < NL; l++) {
        k_layernorm<<<ROWS, 128>>>(x, xln, ln_g + l * DM, ln_b + l * DM);
        k_gemm_tc<0><<<dim3(19, 128), 256>>>(xln, in_w + (size_t)l * DM * DPROJ,
                                             zx, nullptr, ROWS, DPROJ, DM);
        k_conv<<<dim3(10, 32, 16), 128>>>(zx, xbc, conv_w + l * CONVD * 4,
                                          conv_b + l * CONVD);
        k_scan<<<dim3(16, 16), 256>>>(zx, xbc, dt_bias + l * NH,
                                      A_log + l * NH, y);
        k_postscan<<<ROWS, 256>>>(y, xbc, zx, D_par + l * NH, rms_w + l * DI);
        k_gemm_tc<1><<<dim3(4, 128), 256>>>(y, out_w + (size_t)l * DI * DM,
                                            x, x, ROWS, DM, DI);
    }
    k_layernorm<<<ROWS, 128>>>(x, xln, pg, pb);
    k_gemm_tc<2><<<dim3(4, 128), 256>>>(xln, opw, (float*)d_out, opb,
                                        ROWS, DM, DM);
}

// round 4
// speedup vs baseline: 1.1434x; 1.1242x over previous
#include <cuda_runtime.h>
#include <cuda_bf16.h>
#include <math.h>
#include <stdint.h>

#define B_      16
#define L_      1024
#define DM      512
#define DI      1024
#define DSTATE  128
#define NH      16
#define HD      64
#define CONVD   1280
#define DPROJ   2320
#define NL      6
#define ROWS    (B_*L_)   // 16384

// ---------------- scratch (static device allocations) ----------------
__device__ float g_x  [(size_t)ROWS*DM];
__device__ float g_xln[(size_t)ROWS*DM];
__device__ float g_zx [(size_t)ROWS*DPROJ];
__device__ float g_xbc[(size_t)ROWS*CONVD];
__device__ float g_y  [(size_t)ROWS*DI];
__device__ float g_cos[(size_t)L_*256];
__device__ float g_sin[(size_t)L_*256];

// ---------------- small helpers ---------------------------------------
__device__ __forceinline__ unsigned smem_u32(const void* p) {
    return (unsigned)__cvta_generic_to_shared(p);
}
__device__ __forceinline__ unsigned long long f32x2_mul(
        unsigned long long a, unsigned long long b) {
    unsigned long long d;
    asm("mul.rn.f32x2 %0, %1, %2;" : "=l"(d) : "l"(a), "l"(b));
    return d;
}
__device__ __forceinline__ unsigned long long f32x2_fma(
        unsigned long long a, unsigned long long b, unsigned long long c) {
    unsigned long long d;
    asm("fma.rn.f32x2 %0, %1, %2, %3;" : "=l"(d) : "l"(a), "l"(b), "l"(c));
    return d;
}
__device__ __forceinline__ unsigned long long f32x2_dup(float v) {
    unsigned long long d;
    asm("mov.b64 %0, {%1, %2};" : "=l"(d) : "f"(v), "f"(v));
    return d;
}
__device__ __forceinline__ float2 f32x2_unpack(unsigned long long v) {
    float2 r;
    asm("mov.b64 {%0, %1}, %2;" : "=f"(r.x), "=f"(r.y) : "l"(v));
    return r;
}

// ---------------- rope table ------------------------------------------
__global__ void k_rope_tab() {
    int i = blockIdx.x * 256 + threadIdx.x;   // i = l*256 + j
    int l = i >> 8, j = i & 255;
    float invf = (float)pow(10000.0, -(double)j / 256.0);
    float f = (float)l * invf;                // fp32 mult, matches jax rounding
    float s, c;
    sincosf(f, &s, &c);
    g_cos[i] = c;
    g_sin[i] = s;
}

// ---------------- input projection (K=17) + rope ----------------------
__global__ void k_inproj_rope(const float* __restrict__ st,
                              const float* __restrict__ W,
                              const float* __restrict__ bias,
                              float* __restrict__ xout) {
    int row = blockIdx.x;            // b*L + l
    int l   = row & (L_ - 1);
    int j   = threadIdx.x;           // pair index 0..255
    __shared__ float s[17];
    if (j < 17) s[j] = st[row * 17 + j];
    __syncthreads();
    int c0 = j << 1;
    float2 bv = ((const float2*)bias)[j];
    float a0 = bv.x, a1 = bv.y;
#pragma unroll
    for (int i = 0; i < 17; i++) {
        float2 wv = ((const float2*)(W + i * DM))[j];
        a0 = fmaf(s[i], wv.x, a0);
        a1 = fmaf(s[i], wv.y, a1);
    }
    float cs = g_cos[l * 256 + j];
    float sn = g_sin[l * 256 + j];
    xout[(size_t)row * DM + c0]     = a0 * cs - a1 * sn;
    xout[(size_t)row * DM + c0 + 1] = a0 * sn + a1 * cs;
}

// ---------------- layernorm over 512 ---------------------------------
__global__ void __launch_bounds__(128) k_layernorm(
        const float* __restrict__ x, float* __restrict__ out,
        const float* __restrict__ g, const float* __restrict__ b) {
    int row = blockIdx.x;
    int tid = threadIdx.x;           // 128 threads, 4 floats each
    float4 v = ((const float4*)(x + (size_t)row * DM))[tid];
    float s  = v.x + v.y + v.z + v.w;
    float ss = v.x * v.x + v.y * v.y + v.z * v.z + v.w * v.w;
#pragma unroll
    for (int o = 16; o; o >>= 1) {
        s  += __shfl_xor_sync(0xFFFFFFFFu, s, o);
        ss += __shfl_xor_sync(0xFFFFFFFFu, ss, o);
    }
    __shared__ float sw[4], ssw[4];
    if ((tid & 31) == 0) { sw[tid >> 5] = s; ssw[tid >> 5] = ss; }
    __syncthreads();
    s  = sw[0] + sw[1] + sw[2] + sw[3];
    ss = ssw[0] + ssw[1] + ssw[2] + ssw[3];
    float mu  = s * (1.0f / DM);
    float var = ss * (1.0f / DM) - mu * mu;
    float r   = rsqrtf(var + 1e-5f);
    float4 gv = ((const float4*)g)[tid];
    float4 bv = ((const float4*)b)[tid];
    float4 o;
    o.x = (v.x - mu) * r * gv.x + bv.x;
    o.y = (v.y - mu) * r * gv.y + bv.y;
    o.z = (v.z - mu) * r * gv.z + bv.z;
    o.w = (v.w - mu) * r * gv.w + bv.w;
    ((float4*)(out + (size_t)row * DM))[tid] = o;
}

// ---------------- tensor-core GEMM helpers ----------------------------
__device__ __forceinline__ void ldsm_x4(unsigned addr, unsigned &r0, unsigned &r1,
                                        unsigned &r2, unsigned &r3) {
    asm volatile("ldmatrix.sync.aligned.m8n8.x4.shared.b16 {%0,%1,%2,%3}, [%4];"
        : "=r"(r0), "=r"(r1), "=r"(r2), "=r"(r3) : "r"(addr));
}
__device__ __forceinline__ void ldsm_x2(unsigned addr, unsigned &r0, unsigned &r1) {
    asm volatile("ldmatrix.sync.aligned.m8n8.x2.shared.b16 {%0,%1}, [%2];"
        : "=r"(r0), "=r"(r1) : "r"(addr));
}
__device__ __forceinline__ void mma_bf16(float* c, unsigned a0, unsigned a1,
                                         unsigned a2, unsigned a3,
                                         unsigned b0, unsigned b1) {
    asm volatile(
        "mma.sync.aligned.m16n8k16.row.col.f32.bf16.bf16.f32 "
        "{%0,%1,%2,%3}, {%4,%5,%6,%7}, {%8,%9}, {%0,%1,%2,%3};"
        : "+f"(c[0]), "+f"(c[1]), "+f"(c[2]), "+f"(c[3])
        : "r"(a0), "r"(a1), "r"(a2), "r"(a3), "r"(b0), "r"(b1));
}
__device__ __forceinline__ void split_pack(float a, float b,
                                           uint32_t &h, uint32_t &l) {
    __nv_bfloat16 ha = __float2bfloat16(a);
    __nv_bfloat16 hb = __float2bfloat16(b);
    float la = a - __bfloat162float(ha);
    float lb = b - __bfloat162float(hb);
    __nv_bfloat162 hp; hp.x = ha; hp.y = hb;
    __nv_bfloat162 lp; lp.x = __float2bfloat16(la); lp.y = __float2bfloat16(lb);
    h = *reinterpret_cast<uint32_t*>(&hp);
    l = *reinterpret_cast<uint32_t*>(&lp);
}

// ---------------- GEMM 128x128 tile, bf16-split 3-pass MMA ------------
// EPI: 0 = plain, 1 = += residual E[row*N+col], 2 = += bias E[col]
template<int EPI>
__global__ void __launch_bounds__(256, 2) k_gemm_tc(
        const float* __restrict__ A, const float* __restrict__ B,
        float* __restrict__ C, const float* __restrict__ E,
        int M, int N, int K) {
    __shared__ uint32_t As_h[2][128][12];
    __shared__ uint32_t As_l[2][128][12];
    __shared__ uint32_t Bs_h[2][128][12];
    __shared__ uint32_t Bs_l[2][128][12];

    int tid  = threadIdx.x;
    int lane = tid & 31, wid = tid >> 5;
    int wm = wid >> 2, wn = wid & 3;              // warp grid 2 (M) x 4 (N)
    int m0 = blockIdx.y << 7, n0 = blockIdx.x << 7;

    int arow = tid >> 1, aseg = (tid & 1) << 3;
    int brow = tid >> 4, bcol = (tid & 15) << 3;
    const float* Ap = A + (size_t)(m0 + arow) * K + aseg;
    const float* Bp = B + (size_t)brow * N + n0 + bcol;
    bool bok0 = (n0 + bcol     + 3) < N;
    bool bok1 = (n0 + bcol + 4 + 3) < N;

    float4 ra0, ra1, rb0, rb1;
#define LOADG(k0) do {                                                   \
        ra0 = *(const float4*)(Ap + (k0));                               \
        ra1 = *(const float4*)(Ap + (k0) + 4);                           \
        const float* _bp = Bp + (size_t)(k0) * N;                        \
        rb0 = bok0 ? *(const float4*)_bp       : make_float4(0,0,0,0);   \
        rb1 = bok1 ? *(const float4*)(_bp + 4) : make_float4(0,0,0,0);   \
    } while (0)

#define STORE_SMEM(buf) do {                                             \
        int _aw = aseg >> 1;                                             \
        float _fa[8] = {ra0.x, ra0.y, ra0.z, ra0.w,                      \
                        ra1.x, ra1.y, ra1.z, ra1.w};                     \
        _Pragma("unroll")                                                \
        for (int _i = 0; _i < 4; _i++) {                                 \
            uint32_t _h, _l;                                             \
            split_pack(_fa[2*_i], _fa[2*_i+1], _h, _l);                  \
            As_h[buf][arow][_aw + _i] = _h;                              \
            As_l[buf][arow][_aw + _i] = _l;                              \
        }                                                                \
        __nv_bfloat16* _bh = (__nv_bfloat16*)&Bs_h[buf][0][0];           \
        __nv_bfloat16* _bl = (__nv_bfloat16*)&Bs_l[buf][0][0];           \
        float _fb[8] = {rb0.x, rb0.y, rb0.z, rb0.w,                      \
                        rb1.x, rb1.y, rb1.z, rb1.w};                     \
        _Pragma("unroll")                                                \
        for (int _j = 0; _j < 8; _j++) {                                 \
            int _n = bcol + _j;                                          \
            float _v = _fb[_j];                                          \
            __nv_bfloat16 _vh = __float2bfloat16(_v);                    \
            float _vl = _v - __bfloat162float(_vh);                      \
            _bh[_n * 24 + brow] = _vh;                                   \
            _bl[_n * 24 + brow] = __float2bfloat16(_vl);                 \
        }                                                                \
    } while (0)

    LOADG(0);
    STORE_SMEM(0);
    __syncthreads();

    float acc[4][4][4];
#pragma unroll
    for (int i = 0; i < 4; i++)
#pragma unroll
        for (int j = 0; j < 4; j++)
#pragma unroll
            for (int k = 0; k < 4; k++) acc[i][j][k] = 0.0f;

    unsigned offA = (unsigned)((wm * 64 + (lane & 15)) * 48 + ((lane >> 4) & 1) * 16);
    unsigned offB = (unsigned)((wn * 32 + (lane & 7))  * 48 + ((lane >> 3) & 1) * 16);
    unsigned baseAh = smem_u32(&As_h[0][0][0]) + offA;
    unsigned baseAl = smem_u32(&As_l[0][0][0]) + offA;
    unsigned baseBh = smem_u32(&Bs_h[0][0][0]) + offB;
    unsigned baseBl = smem_u32(&Bs_l[0][0][0]) + offB;

    int KT = K >> 4;
    for (int kt = 0; kt < KT; kt++) {
        unsigned cb = (kt & 1) ? 6144u : 0u;
        if (kt + 1 < KT) LOADG((kt + 1) << 4);

        unsigned bh[4][2], bl[4][2];
#pragma unroll
        for (int nt = 0; nt < 4; nt++) {
            ldsm_x2(baseBh + cb + nt * 384, bh[nt][0], bh[nt][1]);
            ldsm_x2(baseBl + cb + nt * 384, bl[nt][0], bl[nt][1]);
        }
#pragma unroll
        for (int mt = 0; mt < 4; mt++) {
            unsigned ah0, ah1, ah2, ah3, al0, al1, al2, al3;
            ldsm_x4(baseAh + cb + mt * 768, ah0, ah1, ah2, ah3);
            ldsm_x4(baseAl + cb + mt * 768, al0, al1, al2, al3);
#pragma unroll
            for (int nt = 0; nt < 4; nt++) {
                mma_bf16(acc[mt][nt], ah0, ah1, ah2, ah3, bh[nt][0], bh[nt][1]);
                mma_bf16(acc[mt][nt], ah0, ah1, ah2, ah3, bl[nt][0], bl[nt][1]);
                mma_bf16(acc[mt][nt], al0, al1, al2, al3, bh[nt][0], bh[nt][1]);
            }
        }
        if (kt + 1 < KT) {
            STORE_SMEM((kt + 1) & 1);
            __syncthreads();
        }
    }
#undef LOADG
#undef STORE_SMEM

#pragma unroll
    for (int mt = 0; mt < 4; mt++) {
        int r0 = m0 + wm * 64 + mt * 16 + (lane >> 2);
#pragma unroll
        for (int nt = 0; nt < 4; nt++) {
            int col = n0 + wn * 32 + nt * 8 + ((lane & 3) << 1);
            if (col < N) {
                size_t i0 = (size_t)r0 * N + col;
                size_t i1 = (size_t)(r0 + 8) * N + col;
                float2 v0 = make_float2(acc[mt][nt][0], acc[mt][nt][1]);
                float2 v1 = make_float2(acc[mt][nt][2], acc[mt][nt][3]);
                if (EPI == 1) {
                    v0.x += E[i0]; v0.y += E[i0 + 1];
                    v1.x += E[i1]; v1.y += E[i1 + 1];
                } else if (EPI == 2) {
                    v0.x += E[col]; v0.y += E[col + 1];
                    v1.x += E[col]; v1.y += E[col + 1];
                }
                *(float2*)(C + i0) = v0;
                *(float2*)(C + i1) = v1;
            }
        }
    }
}

// ---------------- depthwise causal conv (K=4) + silu ------------------
__global__ void k_conv(const float* __restrict__ zx, float* __restrict__ xbc,
                       const float* __restrict__ w, const float* __restrict__ cb) {
    int c  = blockIdx.x * 128 + threadIdx.x;   // 0..1279
    int b  = blockIdx.z;
    int l0 = blockIdx.y * 32;
    float w0 = w[c * 4 + 0], w1 = w[c * 4 + 1];
    float w2 = w[c * 4 + 2], w3 = w[c * 4 + 3];
    float bias = cb[c];
    const float* xin = zx + ((size_t)b * L_) * DPROJ + 1024 + c;
    float* xo = xbc + ((size_t)b * L_) * CONVD + c;
    float x0 = (l0 >= 3) ? xin[(size_t)(l0 - 3) * DPROJ] : 0.0f;
    float x1 = (l0 >= 2) ? xin[(size_t)(l0 - 2) * DPROJ] : 0.0f;
    float x2 = (l0 >= 1) ? xin[(size_t)(l0 - 1) * DPROJ] : 0.0f;
#pragma unroll
    for (int i = 0; i < 32; i++) {
        int l = l0 + i;
        float x3 = xin[(size_t)l * DPROJ];
        float v = bias + w0 * x0 + w1 * x1 + w2 * x2 + w3 * x3;
        v = v / (1.0f + expf(-v));             // silu
        xo[(size_t)l * CONVD] = v;
        x0 = x1; x1 = x2; x2 = x3;
    }
}

// ---------------- sequential selective scan (chunked + f32x2) ---------
// block = (h, b); 256 threads = 64 p x 4 n-groups (32 n each, in regs)
// 16 timesteps staged per cp.async chunk, double buffered.
#define CT 16
__global__ void __launch_bounds__(256) k_scan(
        const float* __restrict__ zx, const float* __restrict__ xbc,
        const float* __restrict__ dt_bias, const float* __restrict__ A_log,
        float* __restrict__ y) {
    int h = blockIdx.x, b = blockIdx.y;
    int tid = threadIdx.x;
    __shared__ float dt_s[L_];
    __shared__ float dec_s[L_];
    __shared__ __align__(16) float stage[2][CT][320];  // [B(128) C(128) x(64)]

    float Ah  = -expf(A_log[h]);
    float dtb = dt_bias[h];
    const float* zrow = zx + ((size_t)b * L_) * DPROJ + 2304 + h;
    for (int l = tid; l < L_; l += 256) {
        float u  = zrow[(size_t)l * DPROJ] + dtb;
        float sp = (u > 20.0f) ? u : log1pf(expf(u));
        dt_s[l]  = sp;
        dec_s[l] = expf(sp * Ah);
    }
    const float* xrow = xbc + ((size_t)b * L_) * CONVD;

    // per-thread cp.async slots: 1280 float4 per chunk = 256 threads x 5
    long  soff[5];
    unsigned doff[5];
#pragma unroll
    for (int k2 = 0; k2 < 5; k2++) {
        int q = k2 * 256 + tid;
        int r = q / 80, s5 = q % 80;            // 80 float4 per row
        int inoff = (s5 < 64) ? (1024 + 4 * s5) : (h * HD + 4 * (s5 - 64));
        int stoff = (s5 < 64) ? (4 * s5) : (256 + 4 * (s5 - 64));
        soff[k2] = (long)r * CONVD + inoff;
        doff[k2] = (unsigned)(r * 320 + stoff) * 4u;
    }
    unsigned sbase = smem_u32(&stage[0][0][0]);
    const unsigned BUFB = CT * 320 * 4;

    // preload chunk 0
#pragma unroll
    for (int k2 = 0; k2 < 5; k2++)
        asm volatile("cp.async.ca.shared.global [%0], [%1], 16;"
            :: "r"(sbase + doff[k2]), "l"(xrow + soff[k2]));
    asm volatile("cp.async.commit_group;");
    asm volatile("cp.async.wait_group 0;");
    __syncthreads();

    int p = tid >> 2, ng = tid & 3;
    unsigned long long S[16];
#pragma unroll
    for (int i = 0; i < 16; i++) S[i] = 0ull;
    float* yout = y + ((size_t)b * L_) * DI + h * HD + p;

    const int NC = L_ / CT;                     // 64 chunks
    for (int c = 0; c < NC; c++) {
        int buf = c & 1;
        if (c + 1 < NC) {
            const float* src = xrow + (size_t)(c + 1) * CT * CONVD;
            unsigned db = sbase + (buf ^ 1) * BUFB;
#pragma unroll
            for (int k2 = 0; k2 < 5; k2++)
                asm volatile("cp.async.ca.shared.global [%0], [%1], 16;"
                    :: "r"(db + doff[k2]), "l"(src + soff[k2]));
            asm volatile("cp.async.commit_group;");
        }
#pragma unroll
        for (int r = 0; r < CT; r++) {
            int l = c * CT + r;
            float dec = dec_s[l];
            float dtx = dt_s[l] * stage[buf][r][256 + p];
            unsigned long long dec2 = f32x2_dup(dec);
            unsigned long long dtx2 = f32x2_dup(dtx);
            const ulonglong2* B2 = (const ulonglong2*)&stage[buf][r][ng * 32];
            const ulonglong2* C2 = (const ulonglong2*)&stage[buf][r][128 + ng * 32];
            unsigned long long acc0 = 0ull, acc1 = 0ull;
#pragma unroll
            for (int i = 0; i < 8; i++) {
                ulonglong2 bq = B2[i], cq = C2[i];
                unsigned long long t0 = f32x2_mul(dtx2, bq.x);
                S[2*i]   = f32x2_fma(S[2*i],   dec2, t0);
                acc0     = f32x2_fma(S[2*i],   cq.x, acc0);
                unsigned long long t1 = f32x2_mul(dtx2, bq.y);
                S[2*i+1] = f32x2_fma(S[2*i+1], dec2, t1);
                acc1     = f32x2_fma(S[2*i+1], cq.y, acc1);
            }
            float2 a0 = f32x2_unpack(acc0);
            float2 a1 = f32x2_unpack(acc1);
            float yp = (a0.x + a0.y) + (a1.x + a1.y);
            yp += __shfl_xor_sync(0xFFFFFFFFu, yp, 1);
            yp += __shfl_xor_sync(0xFFFFFFFFu, yp, 2);
            if (ng == 0) yout[(size_t)l * DI] = yp;
        }
        if (c + 1 < NC) asm volatile("cp.async.wait_group 0;");
        __syncthreads();
    }
}

// ---------------- y = (y + D*xs)*silu(z), RMS-norm, *rms_w ------------
__global__ void __launch_bounds__(256) k_postscan(
        float* __restrict__ y, const float* __restrict__ xbc,
        const float* __restrict__ zx, const float* __restrict__ Dp,
        const float* __restrict__ rmsw) {
    int row = blockIdx.x, tid = threadIdx.x;   // 256 threads, 4 floats each
    float4 yv = ((const float4*)(y   + (size_t)row * DI))[tid];
    float4 xv = ((const float4*)(xbc + (size_t)row * CONVD))[tid];
    float4 zv = ((const float4*)(zx  + (size_t)row * DPROJ))[tid];
    float D = Dp[tid >> 4];
    float4 v;
    v.x = (yv.x + D * xv.x) * (zv.x / (1.0f + expf(-zv.x)));
    v.y = (yv.y + D * xv.y) * (zv.y / (1.0f + expf(-zv.y)));
    v.z = (yv.z + D * xv.z) * (zv.z / (1.0f + expf(-zv.z)));
    v.w = (yv.w + D * xv.w) * (zv.w / (1.0f + expf(-zv.w)));
    float ss = v.x * v.x + v.y * v.y + v.z * v.z + v.w * v.w;
#pragma unroll
    for (int o = 16; o; o >>= 1) ss += __shfl_xor_sync(0xFFFFFFFFu, ss, o);
    __shared__ float sm[8];
    if ((tid & 31) == 0) sm[tid >> 5] = ss;
    __syncthreads();
    float tot = sm[0] + sm[1] + sm[2] + sm[3] + sm[4] + sm[5] + sm[6] + sm[7];
    float sc = rsqrtf(tot * (1.0f / DI) + 1e-5f);
    float4 gw = ((const float4*)rmsw)[tid];
    v.x *= sc * gw.x; v.y *= sc * gw.y; v.z *= sc * gw.z; v.w *= sc * gw.w;
    ((float4*)(y + (size_t)row * DI))[tid] = v;
}

// ---------------- launch ----------------------------------------------
extern "C" void kernel_launch(void* const* d_in, const int* in_sizes, int n_in,
                              void* d_out, int out_size) {
    const float* states  = (const float*)d_in[0];
    const float* ipw     = (const float*)d_in[1];
    const float* ipb     = (const float*)d_in[2];
    const float* ln_g    = (const float*)d_in[3];
    const float* ln_b    = (const float*)d_in[4];
    const float* in_w    = (const float*)d_in[5];
    const float* conv_w  = (const float*)d_in[6];
    const float* conv_b  = (const float*)d_in[7];
    const float* dt_bias = (const float*)d_in[8];
    const float* A_log   = (const float*)d_in[9];
    const float* D_par   = (const float*)d_in[10];
    const float* rms_w   = (const float*)d_in[11];
    const float* out_w   = (const float*)d_in[12];
    const float* pg      = (const float*)d_in[13];
    const float* pb      = (const float*)d_in[14];
    const float* opw     = (const float*)d_in[15];
    const float* opb     = (const float*)d_in[16];

    float *x, *xln, *zx, *xbc, *y;
    cudaGetSymbolAddress((void**)&x,   g_x);
    cudaGetSymbolAddress((void**)&xln, g_xln);
    cudaGetSymbolAddress((void**)&zx,  g_zx);
    cudaGetSymbolAddress((void**)&xbc, g_xbc);
    cudaGetSymbolAddress((void**)&y,   g_y);

    k_rope_tab<<<L_, 256>>>();
    k_inproj_rope<<<ROWS, 256>>>(states, ipw, ipb, x);

    for (int l = 0; l < NL; l++) {
        k_layernorm<<<ROWS, 128>>>(x, xln, ln_g + l * DM, ln_b + l * DM);
        k_gemm_tc<0><<<dim3(19, 128), 256>>>(xln, in_w + (size_t)l * DM * DPROJ,
                                             zx, nullptr, ROWS, DPROJ, DM);
        k_conv<<<dim3(10, 32, 16), 128>>>(zx, xbc, conv_w + l * CONVD * 4,
                                          conv_b + l * CONVD);
        k_scan<<<dim3(16, 16), 256>>>(zx, xbc, dt_bias + l * NH,
                                      A_log + l * NH, y);
        k_postscan<<<ROWS, 256>>>(y, xbc, zx, D_par + l * NH, rms_w + l * DI);
        k_gemm_tc<1><<<dim3(4, 128), 256>>>(y, out_w + (size_t)l * DI * DM,
                                            x, x, ROWS, DM, DI);
    }
    k_layernorm<<<ROWS, 128>>>(x, xln, pg, pb);
    k_gemm_tc<2><<<dim3(4, 128), 256>>>(xln, opw, (float*)d_out, opb,
                                        ROWS, DM, DM);
}

// round 5
// speedup vs baseline: 3.1921x; 2.7919x over previous
#include <cuda_runtime.h>
#include <cuda_bf16.h>
#include <math.h>
#include <stdint.h>

#define B_      16
#define L_      1024
#define DM      512
#define DI      1024
#define DSTATE  128
#define NH      16
#define HD      64
#define CONVD   1280
#define DPROJ   2320
#define NL      6
#define ROWS    (B_*L_)   // 16384

// weight split offsets (transposed [N][K] bf16)
#define WIN_SZ   (DPROJ*DM)          // 2320*512 per layer
#define WOUT_SZ  (DM*DI)             // 512*1024 per layer
#define WIN_OFF(l)   ((size_t)(l)*WIN_SZ)
#define WOUT_OFF(l)  ((size_t)(NL*WIN_SZ) + (size_t)(l)*WOUT_SZ)
#define WFIN_OFF     ((size_t)(NL*WIN_SZ) + (size_t)(NL*WOUT_SZ))
#define WTOT         (WFIN_OFF + DM*DM)

// ---------------- scratch (static device allocations) ----------------
__device__ float g_x  [(size_t)ROWS*DM];
__device__ float g_zx [(size_t)ROWS*DPROJ];
__device__ float g_xbc[(size_t)ROWS*CONVD];
__device__ float g_y  [(size_t)ROWS*DI];
__device__ float g_cos[(size_t)L_*256];
__device__ float g_sin[(size_t)L_*256];
__device__ __nv_bfloat16 g_Ah[(size_t)ROWS*DI];
__device__ __nv_bfloat16 g_Al[(size_t)ROWS*DI];
__device__ __nv_bfloat16 g_Wh[WTOT];
__device__ __nv_bfloat16 g_Wl[WTOT];

// ---------------- small helpers ---------------------------------------
__device__ __forceinline__ unsigned smem_u32(const void* p) {
    return (unsigned)__cvta_generic_to_shared(p);
}
__device__ __forceinline__ unsigned long long f32x2_mul(
        unsigned long long a, unsigned long long b) {
    unsigned long long d;
    asm("mul.rn.f32x2 %0, %1, %2;" : "=l"(d) : "l"(a), "l"(b));
    return d;
}
__device__ __forceinline__ unsigned long long f32x2_fma(
        unsigned long long a, unsigned long long b, unsigned long long c) {
    unsigned long long d;
    asm("fma.rn.f32x2 %0, %1, %2, %3;" : "=l"(d) : "l"(a), "l"(b), "l"(c));
    return d;
}
__device__ __forceinline__ unsigned long long f32x2_dup(float v) {
    unsigned long long d;
    asm("mov.b64 %0, {%1, %2};" : "=l"(d) : "f"(v), "f"(v));
    return d;
}
__device__ __forceinline__ float2 f32x2_unpack(unsigned long long v) {
    float2 r;
    asm("mov.b64 {%0, %1}, %2;" : "=f"(r.x), "=f"(r.y) : "l"(v));
    return r;
}
__device__ __forceinline__ void split_pack(float a, float b,
                                           uint32_t &h, uint32_t &l) {
    __nv_bfloat16 ha = __float2bfloat16(a);
    __nv_bfloat16 hb = __float2bfloat16(b);
    float la = a - __bfloat162float(ha);
    float lb = b - __bfloat162float(hb);
    __nv_bfloat162 hp; hp.x = ha; hp.y = hb;
    __nv_bfloat162 lp; lp.x = __float2bfloat16(la); lp.y = __float2bfloat16(lb);
    h = *reinterpret_cast<uint32_t*>(&hp);
    l = *reinterpret_cast<uint32_t*>(&lp);
}

// ---------------- rope table ------------------------------------------
__global__ void k_rope_tab() {
    int i = blockIdx.x * 256 + threadIdx.x;
    int l = i >> 8, j = i & 255;
    float invf = (float)pow(10000.0, -(double)j / 256.0);
    float f = (float)l * invf;
    float s, c;
    sincosf(f, &s, &c);
    g_cos[i] = c;
    g_sin[i] = s;
}

// ---------------- input projection (K=17) + rope ----------------------
__global__ void k_inproj_rope(const float* __restrict__ st,
                              const float* __restrict__ W,
                              const float* __restrict__ bias,
                              float* __restrict__ xout) {
    int row = blockIdx.x;
    int l   = row & (L_ - 1);
    int j   = threadIdx.x;
    __shared__ float s[17];
    if (j < 17) s[j] = st[row * 17 + j];
    __syncthreads();
    int c0 = j << 1;
    float2 bv = ((const float2*)bias)[j];
    float a0 = bv.x, a1 = bv.y;
#pragma unroll
    for (int i = 0; i < 17; i++) {
        float2 wv = ((const float2*)(W + i * DM))[j];
        a0 = fmaf(s[i], wv.x, a0);
        a1 = fmaf(s[i], wv.y, a1);
    }
    float cs = g_cos[l * 256 + j];
    float sn = g_sin[l * 256 + j];
    xout[(size_t)row * DM + c0]     = a0 * cs - a1 * sn;
    xout[(size_t)row * DM + c0 + 1] = a0 * sn + a1 * cs;
}

// ---------------- weight split + transpose (one-time) ------------------
// W: [K][N] fp32 row-major -> hiT/loT: [N][K] bf16
__global__ void k_splitWT(const float* __restrict__ W,
                          __nv_bfloat16* __restrict__ hiT,
                          __nv_bfloat16* __restrict__ loT, int K, int N) {
    __shared__ float t[32][33];
    int n0 = blockIdx.x * 32, k0 = blockIdx.y * 32;
    int tx = threadIdx.x, ty = threadIdx.y;   // 32 x 8
#pragma unroll
    for (int i = 0; i < 32; i += 8) {
        int k = k0 + ty + i, n = n0 + tx;
        t[ty + i][tx] = (k < K && n < N) ? W[(size_t)k * N + n] : 0.0f;
    }
    __syncthreads();
#pragma unroll
    for (int i = 0; i < 32; i += 8) {
        int n = n0 + ty + i, k = k0 + tx;
        if (n < N && k < K) {
            float v = t[tx][ty + i];
            __nv_bfloat16 h = __float2bfloat16(v);
            hiT[(size_t)n * K + k] = h;
            loT[(size_t)n * K + k] = __float2bfloat16(v - __bfloat162float(h));
        }
    }
}

// ---------------- layernorm over 512 -> bf16 hi/lo ---------------------
__global__ void __launch_bounds__(128) k_layernorm(
        const float* __restrict__ x,
        __nv_bfloat16* __restrict__ ah, __nv_bfloat16* __restrict__ al,
        const float* __restrict__ g, const float* __restrict__ b) {
    int row = blockIdx.x;
    int tid = threadIdx.x;
    float4 v = ((const float4*)(x + (size_t)row * DM))[tid];
    float s  = v.x + v.y + v.z + v.w;
    float ss = v.x * v.x + v.y * v.y + v.z * v.z + v.w * v.w;
#pragma unroll
    for (int o = 16; o; o >>= 1) {
        s  += __shfl_xor_sync(0xFFFFFFFFu, s, o);
        ss += __shfl_xor_sync(0xFFFFFFFFu, ss, o);
    }
    __shared__ float sw[4], ssw[4];
    if ((tid & 31) == 0) { sw[tid >> 5] = s; ssw[tid >> 5] = ss; }
    __syncthreads();
    s  = sw[0] + sw[1] + sw[2] + sw[3];
    ss = ssw[0] + ssw[1] + ssw[2] + ssw[3];
    float mu  = s * (1.0f / DM);
    float var = ss * (1.0f / DM) - mu * mu;
    float r   = rsqrtf(var + 1e-5f);
    float4 gv = ((const float4*)g)[tid];
    float4 bv = ((const float4*)b)[tid];
    float4 o;
    o.x = (v.x - mu) * r * gv.x + bv.x;
    o.y = (v.y - mu) * r * gv.y + bv.y;
    o.z = (v.z - mu) * r * gv.z + bv.z;
    o.w = (v.w - mu) * r * gv.w + bv.w;
    uint32_t h0, l0, h1, l1;
    split_pack(o.x, o.y, h0, l0);
    split_pack(o.z, o.w, h1, l1);
    *(uint2*)(ah + (size_t)row * DM + 4 * tid) = make_uint2(h0, h1);
    *(uint2*)(al + (size_t)row * DM + 4 * tid) = make_uint2(l0, l1);
}

// ---------------- tensor-core GEMM helpers ----------------------------
__device__ __forceinline__ void ldsm_x4(unsigned addr, unsigned &r0, unsigned &r1,
                                        unsigned &r2, unsigned &r3) {
    asm volatile("ldmatrix.sync.aligned.m8n8.x4.shared.b16 {%0,%1,%2,%3}, [%4];"
        : "=r"(r0), "=r"(r1), "=r"(r2), "=r"(r3) : "r"(addr));
}
__device__ __forceinline__ void ldsm_x2(unsigned addr, unsigned &r0, unsigned &r1) {
    asm volatile("ldmatrix.sync.aligned.m8n8.x2.shared.b16 {%0,%1}, [%2];"
        : "=r"(r0), "=r"(r1) : "r"(addr));
}
__device__ __forceinline__ void mma_bf16(float* c, unsigned a0, unsigned a1,
                                         unsigned a2, unsigned a3,
                                         unsigned b0, unsigned b1) {
    asm volatile(
        "mma.sync.aligned.m16n8k16.row.col.f32.bf16.bf16.f32 "
        "{%0,%1,%2,%3}, {%4,%5,%6,%7}, {%8,%9}, {%0,%1,%2,%3};"
        : "+f"(c[0]), "+f"(c[1]), "+f"(c[2]), "+f"(c[3])
        : "r"(a0), "r"(a1), "r"(a2), "r"(a3), "r"(b0), "r"(b1));
}

// ---------------- GEMM 128x128 tile, pre-split bf16, cp.async 3-stage --
// A hi/lo: [M][K] bf16.  B hi/lo: [N][K] bf16 (pre-transposed).
// EPI: 0 = plain, 1 = += residual E[row*N+col], 2 = += bias E[col]
// stage layout: Ah(6144) Al(6144) Bh(6144) Bl(6144) = 24576 B; 3 stages.
#define GSTG 24576u
template<int EPI>
__global__ void __launch_bounds__(256, 2) k_gemm_bf(
        const __nv_bfloat16* __restrict__ Ah, const __nv_bfloat16* __restrict__ Al,
        const __nv_bfloat16* __restrict__ Bh, const __nv_bfloat16* __restrict__ Bl,
        float* __restrict__ C, const float* __restrict__ E,
        int M, int N, int K) {
    extern __shared__ __align__(16) char dynsm[];
    int tid  = threadIdx.x;
    int lane = tid & 31, wid = tid >> 5;
    int wm = wid >> 2, wn = wid & 3;
    int m0 = blockIdx.y << 7, n0 = blockIdx.x << 7;

    // loader mapping: each thread cp.asyncs one 16B chunk per tile per stage
    int r2 = tid >> 1, cc = tid & 1;
    const __nv_bfloat16* sAh = Ah + (size_t)(m0 + r2) * K + cc * 8;
    const __nv_bfloat16* sAl = Al + (size_t)(m0 + r2) * K + cc * 8;
    bool bok = (n0 + r2) < N;
    int brow = bok ? (n0 + r2) : 0;
    const __nv_bfloat16* sBh = Bh + (size_t)brow * K + cc * 8;
    const __nv_bfloat16* sBl = Bl + (size_t)brow * K + cc * 8;
    int bsz = bok ? 16 : 0;
    unsigned dsm = smem_u32(dynsm);
    unsigned dA  = dsm + (unsigned)(r2 * 48 + cc * 16);

#define ISSUE(slot, k0) do {                                              \
        unsigned _b = dA + (unsigned)(slot) * GSTG;                       \
        asm volatile("cp.async.ca.shared.global [%0], [%1], 16;"          \
            :: "r"(_b),          "l"(sAh + (k0)));                        \
        asm volatile("cp.async.ca.shared.global [%0], [%1], 16;"          \
            :: "r"(_b + 6144u),  "l"(sAl + (k0)));                        \
        asm volatile("cp.async.ca.shared.global [%0], [%1], 16, %2;"      \
            :: "r"(_b + 12288u), "l"(sBh + (k0)), "r"(bsz));              \
        asm volatile("cp.async.ca.shared.global [%0], [%1], 16, %2;"      \
            :: "r"(_b + 18432u), "l"(sBl + (k0)), "r"(bsz));              \
    } while (0)

    int KT = K >> 4;
    ISSUE(0, 0);
    asm volatile("cp.async.commit_group;");
    ISSUE(1, 16);
    asm volatile("cp.async.commit_group;");

    float acc[4][4][4];
#pragma unroll
    for (int i = 0; i < 4; i++)
#pragma unroll
        for (int j = 0; j < 4; j++)
#pragma unroll
            for (int k = 0; k < 4; k++) acc[i][j][k] = 0.0f;

    unsigned offA = (unsigned)((wm * 64 + (lane & 15)) * 48 + ((lane >> 4) & 1) * 16);
    unsigned offB = (unsigned)((wn * 32 + (lane & 7))  * 48 + ((lane >> 3) & 1) * 16);
    unsigned baseAh = dsm + offA;
    unsigned baseAl = dsm + 6144u  + offA;
    unsigned baseBh = dsm + 12288u + offB;
    unsigned baseBl = dsm + 18432u + offB;

    int slot = 0;
    for (int kt = 0; kt < KT; kt++) {
        asm volatile("cp.async.wait_group 1;");
        __syncthreads();
        unsigned cb = (unsigned)slot * GSTG;

        unsigned bh[4][2], bl[4][2];
#pragma unroll
        for (int nt = 0; nt < 4; nt++) {
            ldsm_x2(baseBh + cb + nt * 384, bh[nt][0], bh[nt][1]);
            ldsm_x2(baseBl + cb + nt * 384, bl[nt][0], bl[nt][1]);
        }
#pragma unroll
        for (int mt = 0; mt < 4; mt++) {
            unsigned ah0, ah1, ah2, ah3, al0, al1, al2, al3;
            ldsm_x4(baseAh + cb + mt * 768, ah0, ah1, ah2, ah3);
            ldsm_x4(baseAl + cb + mt * 768, al0, al1, al2, al3);
#pragma unroll
            for (int nt = 0; nt < 4; nt++) {
                mma_bf16(acc[mt][nt], ah0, ah1, ah2, ah3, bh[nt][0], bh[nt][1]);
                mma_bf16(acc[mt][nt], ah0, ah1, ah2, ah3, bl[nt][0], bl[nt][1]);
                mma_bf16(acc[mt][nt], al0, al1, al2, al3, bh[nt][0], bh[nt][1]);
            }
        }
        int ktn = kt + 2;
        if (ktn < KT) {
            int sl2 = slot;          // (kt+2) % 3 == (kt-1) % 3; compute below
            sl2 = slot + 2; if (sl2 >= 3) sl2 -= 3;
            ISSUE(sl2, ktn << 4);
        }
        asm volatile("cp.async.commit_group;");
        if (++slot == 3) slot = 0;
    }
#undef ISSUE

#pragma unroll
    for (int mt = 0; mt < 4; mt++) {
        int r0 = m0 + wm * 64 + mt * 16 + (lane >> 2);
#pragma unroll
        for (int nt = 0; nt < 4; nt++) {
            int col = n0 + wn * 32 + nt * 8 + ((lane & 3) << 1);
            if (col < N) {
                size_t i0 = (size_t)r0 * N + col;
                size_t i1 = (size_t)(r0 + 8) * N + col;
                float2 v0 = make_float2(acc[mt][nt][0], acc[mt][nt][1]);
                float2 v1 = make_float2(acc[mt][nt][2], acc[mt][nt][3]);
                if (EPI == 1) {
                    v0.x += E[i0]; v0.y += E[i0 + 1];
                    v1.x += E[i1]; v1.y += E[i1 + 1];
                } else if (EPI == 2) {
                    v0.x += E[col]; v0.y += E[col + 1];
                    v1.x += E[col]; v1.y += E[col + 1];
                }
                *(float2*)(C + i0) = v0;
                *(float2*)(C + i1) = v1;
            }
        }
    }
}

// ---------------- depthwise causal conv (K=4) + silu ------------------
__global__ void k_conv(const float* __restrict__ zx, float* __restrict__ xbc,
                       const float* __restrict__ w, const float* __restrict__ cb) {
    int c  = blockIdx.x * 128 + threadIdx.x;
    int b  = blockIdx.z;
    int l0 = blockIdx.y * 32;
    float w0 = w[c * 4 + 0], w1 = w[c * 4 + 1];
    float w2 = w[c * 4 + 2], w3 = w[c * 4 + 3];
    float bias = cb[c];
    const float* xin = zx + ((size_t)b * L_) * DPROJ + 1024 + c;
    float* xo = xbc + ((size_t)b * L_) * CONVD + c;
    float x0 = (l0 >= 3) ? xin[(size_t)(l0 - 3) * DPROJ] : 0.0f;
    float x1 = (l0 >= 2) ? xin[(size_t)(l0 - 2) * DPROJ] : 0.0f;
    float x2 = (l0 >= 1) ? xin[(size_t)(l0 - 1) * DPROJ] : 0.0f;
#pragma unroll
    for (int i = 0; i < 32; i++) {
        int l = l0 + i;
        float x3 = xin[(size_t)l * DPROJ];
        float v = bias + w0 * x0 + w1 * x1 + w2 * x2 + w3 * x3;
        v = v / (1.0f + expf(-v));
        xo[(size_t)l * CONVD] = v;
        x0 = x1; x1 = x2; x2 = x3;
    }
}

// ---------------- sequential selective scan (chunked, swizzled) --------
// block = (h, b); 256 threads = 64 p x 4 n-groups (32 n each, in regs)
// B/C float4 j stored at slot (j&~7)|((j&7)^(j>>3)) -> the 4 ng-groups hit
// 4 distinct 16B bank groups (offsets {0,16,32,48} mod 128). x untouched.
#define CT 16
__global__ void __launch_bounds__(256) k_scan(
        const float* __restrict__ zx, const float* __restrict__ xbc,
        const float* __restrict__ dt_bias, const float* __restrict__ A_log,
        float* __restrict__ y) {
    int h = blockIdx.x, b = blockIdx.y;
    int tid = threadIdx.x;
    __shared__ float dt_s[L_];
    __shared__ float dec_s[L_];
    __shared__ __align__(16) float stage[2][CT][320];

    float Ah  = -expf(A_log[h]);
    float dtb = dt_bias[h];
    const float* zrow = zx + ((size_t)b * L_) * DPROJ + 2304 + h;
    for (int l = tid; l < L_; l += 256) {
        float u  = zrow[(size_t)l * DPROJ] + dtb;
        float sp = (u > 20.0f) ? u : log1pf(expf(u));
        dt_s[l]  = sp;
        dec_s[l] = expf(sp * Ah);
    }
    const float* xrow = xbc + ((size_t)b * L_) * CONVD;

    // cp.async staging: 1280 float4 per chunk = 256 threads x 5, swizzled dest
    long  soff[5];
    unsigned doff[5];
#pragma unroll
    for (int k2 = 0; k2 < 5; k2++) {
        int q = k2 * 256 + tid;
        int r = q / 80, s5 = q % 80;
        int slot, inoff;
        if (s5 < 32) {
            slot  = (s5 & 0x18) | ((s5 & 7) ^ (s5 >> 3));
            inoff = 1024 + 4 * s5;
        } else if (s5 < 64) {
            int t = s5 - 32;
            slot  = 32 + ((t & 0x18) | ((t & 7) ^ (t >> 3)));
            inoff = 1024 + 4 * s5;
        } else {
            slot  = s5;
            inoff = h * HD + 4 * (s5 - 64);
        }
        soff[k2] = (long)r * CONVD + inoff;
        doff[k2] = (unsigned)((r * 80 + slot) * 16);
    }
    unsigned sbase = smem_u32(&stage[0][0][0]);
    const unsigned BUFB = CT * 320 * 4;

#pragma unroll
    for (int k2 = 0; k2 < 5; k2++)
        asm volatile("cp.async.ca.shared.global [%0], [%1], 16;"
            :: "r"(sbase + doff[k2]), "l"(xrow + soff[k2]));
    asm volatile("cp.async.commit_group;");
    asm volatile("cp.async.wait_group 0;");
    __syncthreads();

    int p = tid >> 2, ng = tid & 3;
    int sB[8], sC[8];
#pragma unroll
    for (int i = 0; i < 8; i++) {
        sB[i] = (ng * 8 + (i ^ ng)) * 16;
        sC[i] = sB[i] + 512;
    }
    unsigned long long S[16];
#pragma unroll
    for (int i = 0; i < 16; i++) S[i] = 0ull;
    float* yout = y + ((size_t)b * L_) * DI + h * HD + p;

    const int NC = L_ / CT;
    for (int c = 0; c < NC; c++) {
        int buf = c & 1;
        if (c + 1 < NC) {
            const float* src = xrow + (size_t)(c + 1) * CT * CONVD;
            unsigned db = sbase + (buf ^ 1) * BUFB;
#pragma unroll
            for (int k2 = 0; k2 < 5; k2++)
                asm volatile("cp.async.ca.shared.global [%0], [%1], 16;"
                    :: "r"(db + doff[k2]), "l"(src + soff[k2]));
            asm volatile("cp.async.commit_group;");
        }
#pragma unroll
        for (int r = 0; r < CT; r++) {
            int l = c * CT + r;
            const char* rowp = (const char*)&stage[buf][r][0];
            float dec = dec_s[l];
            float dtx = dt_s[l] * *(const float*)(rowp + (256 + p) * 4);
            unsigned long long dec2 = f32x2_dup(dec);
            unsigned long long dtx2 = f32x2_dup(dtx);
            unsigned long long acc0 = 0ull, acc1 = 0ull;
#pragma unroll
            for (int i = 0; i < 8; i++) {
                ulonglong2 bq = *(const ulonglong2*)(rowp + sB[i]);
                ulonglong2 cq = *(const ulonglong2*)(rowp + sC[i]);
                unsigned long long t0 = f32x2_mul(dtx2, bq.x);
                S[2*i]   = f32x2_fma(S[2*i],   dec2, t0);
                acc0     = f32x2_fma(S[2*i],   cq.x, acc0);
                unsigned long long t1 = f32x2_mul(dtx2, bq.y);
                S[2*i+1] = f32x2_fma(S[2*i+1], dec2, t1);
                acc1     = f32x2_fma(S[2*i+1], cq.y, acc1);
            }
            float2 a0 = f32x2_unpack(acc0);
            float2 a1 = f32x2_unpack(acc1);
            float yp = (a0.x + a0.y) + (a1.x + a1.y);
            yp += __shfl_xor_sync(0xFFFFFFFFu, yp, 1);
            yp += __shfl_xor_sync(0xFFFFFFFFu, yp, 2);
            if (ng == 0) yout[(size_t)l * DI] = yp;
        }
        if (c + 1 < NC) asm volatile("cp.async.wait_group 0;");
        __syncthreads();
    }
}

// ---------------- y=(y+D*xs)*silu(z), RMS-norm, *rms_w -> bf16 hi/lo ---
__global__ void __launch_bounds__(256) k_postscan(
        const float* __restrict__ y, const float* __restrict__ xbc,
        const float* __restrict__ zx, const float* __restrict__ Dp,
        const float* __restrict__ rmsw,
        __nv_bfloat16* __restrict__ ah, __nv_bfloat16* __restrict__ al) {
    int row = blockIdx.x, tid = threadIdx.x;
    float4 yv = ((const float4*)(y   + (size_t)row * DI))[tid];
    float4 xv = ((const float4*)(xbc + (size_t)row * CONVD))[tid];
    float4 zv = ((const float4*)(zx  + (size_t)row * DPROJ))[tid];
    float D = Dp[tid >> 4];
    float4 v;
    v.x = (yv.x + D * xv.x) * (zv.x / (1.0f + expf(-zv.x)));
    v.y = (yv.y + D * xv.y) * (zv.y / (1.0f + expf(-zv.y)));
    v.z = (yv.z + D * xv.z) * (zv.z / (1.0f + expf(-zv.z)));
    v.w = (yv.w + D * xv.w) * (zv.w / (1.0f + expf(-zv.w)));
    float ss = v.x * v.x + v.y * v.y + v.z * v.z + v.w * v.w;
#pragma unroll
    for (int o = 16; o; o >>= 1) ss += __shfl_xor_sync(0xFFFFFFFFu, ss, o);
    __shared__ float sm[8];
    if ((tid & 31) == 0) sm[tid >> 5] = ss;
    __syncthreads();
    float tot = sm[0] + sm[1] + sm[2] + sm[3] + sm[4] + sm[5] + sm[6] + sm[7];
    float sc = rsqrtf(tot * (1.0f / DI) + 1e-5f);
    float4 gw = ((const float4*)rmsw)[tid];
    v.x *= sc * gw.x; v.y *= sc * gw.y; v.z *= sc * gw.z; v.w *= sc * gw.w;
    uint32_t h0, l0, h1, l1;
    split_pack(v.x, v.y, h0, l0);
    split_pack(v.z, v.w, h1, l1);
    *(uint2*)(ah + (size_t)row * DI + 4 * tid) = make_uint2(h0, h1);
    *(uint2*)(al + (size_t)row * DI + 4 * tid) = make_uint2(l0, l1);
}

// ---------------- launch ----------------------------------------------
extern "C" void kernel_launch(void* const* d_in, const int* in_sizes, int n_in,
                              void* d_out, int out_size) {
    const float* states  = (const float*)d_in[0];
    const float* ipw     = (const float*)d_in[1];
    const float* ipb     = (const float*)d_in[2];
    const float* ln_g    = (const float*)d_in[3];
    const float* ln_b    = (const float*)d_in[4];
    const float* in_w    = (const float*)d_in[5];
    const float* conv_w  = (const float*)d_in[6];
    const float* conv_b  = (const float*)d_in[7];
    const float* dt_bias = (const float*)d_in[8];
    const float* A_log   = (const float*)d_in[9];
    const float* D_par   = (const float*)d_in[10];
    const float* rms_w   = (const float*)d_in[11];
    const float* out_w   = (const float*)d_in[12];
    const float* pg      = (const float*)d_in[13];
    const float* pb      = (const float*)d_in[14];
    const float* opw     = (const float*)d_in[15];
    const float* opb     = (const float*)d_in[16];

    float *x, *zx, *xbc, *y;
    __nv_bfloat16 *ah, *al, *wh, *wl;
    cudaGetSymbolAddress((void**)&x,   g_x);
    cudaGetSymbolAddress((void**)&zx,  g_zx);
    cudaGetSymbolAddress((void**)&xbc, g_xbc);
    cudaGetSymbolAddress((void**)&y,   g_y);
    cudaGetSymbolAddress((void**)&ah,  g_Ah);
    cudaGetSymbolAddress((void**)&al,  g_Al);
    cudaGetSymbolAddress((void**)&wh,  g_Wh);
    cudaGetSymbolAddress((void**)&wl,  g_Wl);

    cudaFuncSetAttribute(k_gemm_bf<0>, cudaFuncAttributeMaxDynamicSharedMemorySize, 3 * GSTG);
    cudaFuncSetAttribute(k_gemm_bf<1>, cudaFuncAttributeMaxDynamicSharedMemorySize, 3 * GSTG);
    cudaFuncSetAttribute(k_gemm_bf<2>, cudaFuncAttributeMaxDynamicSharedMemorySize, 3 * GSTG);

    // one-time weight split+transpose
    for (int l = 0; l < NL; l++) {
        k_splitWT<<<dim3((DPROJ + 31) / 32, DM / 32), dim3(32, 8)>>>(
            in_w + (size_t)l * DM * DPROJ, wh + WIN_OFF(l), wl + WIN_OFF(l), DM, DPROJ);
        k_splitWT<<<dim3(DM / 32, DI / 32), dim3(32, 8)>>>(
            out_w + (size_t)l * DI * DM, wh + WOUT_OFF(l), wl + WOUT_OFF(l), DI, DM);
    }
    k_splitWT<<<dim3(DM / 32, DM / 32), dim3(32, 8)>>>(
        opw, wh + WFIN_OFF, wl + WFIN_OFF, DM, DM);

    k_rope_tab<<<L_, 256>>>();
    k_inproj_rope<<<ROWS, 256>>>(states, ipw, ipb, x);

    for (int l = 0; l < NL; l++) {
        k_layernorm<<<ROWS, 128>>>(x, ah, al, ln_g + l * DM, ln_b + l * DM);
        k_gemm_bf<0><<<dim3(19, 128), 256, 3 * GSTG>>>(
            ah, al, wh + WIN_OFF(l), wl + WIN_OFF(l), zx, nullptr, ROWS, DPROJ, DM);
        k_conv<<<dim3(10, 32, 16), 128>>>(zx, xbc, conv_w + l * CONVD * 4,
                                          conv_b + l * CONVD);
        k_scan<<<dim3(16, 16), 256>>>(zx, xbc, dt_bias + l * NH,
                                      A_log + l * NH, y);
        k_postscan<<<ROWS, 256>>>(y, xbc, zx, D_par + l * NH, rms_w + l * DI,
                                  ah, al);
        k_gemm_bf<1><<<dim3(4, 128), 256, 3 * GSTG>>>(
            ah, al, wh + WOUT_OFF(l), wl + WOUT_OFF(l), x, x, ROWS, DM, DI);
    }
    k_layernorm<<<ROWS, 128>>>(x, ah, al, pg, pb);
    k_gemm_bf<2><<<dim3(4, 128), 256, 3 * GSTG>>>(
        ah, al, wh + WFIN_OFF, wl + WFIN_OFF, (float*)d_out, opb, ROWS, DM, DM);
}